// round 14
// baseline (speedup 1.0000x reference)
#include <cuda_runtime.h>

#define Bz 8
#define Nn 65536
#define Ee 32
#define Kk 33
#define BPB 32             // blocks per batch
#define PPB 2048           // points per block (no tail)
#define TT 512
#define WW (TT / 32)       // 16 warps
#define GRID (Bz * BPB)    // 256 blocks; all resident at 2 blocks/SM

#define DELTA_V 0.5f
#define DELTA_D 1.5f
#define GAMMA 0.001f
#define EPSX 1e-12f
#define FULLM 0xFFFFFFFFu

// Scratch (allocation-free rule: __device__ globals, zero-init at load;
// cleaned/overwritten each run so graph replays stay deterministic).
__device__ float4 g_sums4[Bz * Kk * 8];   // [b][k][e/4]
__device__ float  g_counts[Bz * Kk];
__device__ float  g_var[Bz];              // sum over points of hinge/count[label]
__device__ float  g_part[Bz];             // per-batch loss (overwritten each run)
__device__ int    g_ctr[Bz];              // finalize election (reset each run)
__device__ unsigned int g_syncb[Bz];      // per-batch monotone ticket counters
__device__ unsigned int g_fin;            // monotone finalize ticket

// ---------------------------------------------------------------------------
// Fused persistent kernel: phase 1 (sums/counts, labels cached to smem) ->
// per-batch ticket sync -> phase 2 (weighted hinge, labels from smem) ->
// per-batch finalize -> last finalizer stores out[0].
// ---------------------------------------------------------------------------
__global__ void __launch_bounds__(TT, 2) fused_kernel(const float4* __restrict__ emb4,
                                                      const int* __restrict__ lab,
                                                      float* __restrict__ out) {
    // dynamic smem: phase-1 per-warp accumulators; phase 2 reuses the front
    // of this region for the center table (merge is complete by then).
    extern __shared__ char dyn[];
    float4 (*s_sum)[Kk * 8] = (float4 (*)[Kk * 8])dyn;
    float  (*s_cnt1)[Kk]    = (float (*)[Kk])(dyn + (size_t)WW * Kk * 8 * sizeof(float4));
    float4* s_c = (float4*)dyn;              // phase-2 alias: centers [Kk*8]

    // packed label cache: word (p0>>4)*4 + sub holds the 4 labels lane-group
    // (sub) touches in iteration starting at p0 (points p0+sub+{0,4,8,12}).
    __shared__ unsigned s_lab32[PPB / 4];    // 2KB

    __shared__ float s_cnt[Kk];
    __shared__ float s_w[Kk];                // (k>0) ? 1/count : 0
    __shared__ float red[3][WW];
    __shared__ int   s_flag;

    int tid = threadIdx.x;
    int w = tid >> 5;
    int lane = tid & 31;
    int sub = lane >> 3;     // which of 4 points in a quarter
    int l8  = lane & 7;      // float4 slot within the point

    int b = blockIdx.x / BPB;
    int base = b * Nn + (blockIdx.x % BPB) * PPB;

    // ================= PHASE 1: segment sums + counts =================
    for (int i = lane; i < Kk * 8; i += 32) s_sum[w][i] = make_float4(0.f, 0.f, 0.f, 0.f);
    for (int i = lane; i < Kk; i += 32) s_cnt1[w][i] = 0.f;
    __syncwarp();

    for (int p0 = w * 16; p0 < PPB; p0 += WW * 16) {     // 16 pts/warp-iter, 8 iters
        int gp = base + p0 + sub;
        // front-batched loads: 4x LDG.128 + 4 labels in flight
        float4 v0 = emb4[(size_t)(gp     ) * 8 + l8];
        float4 v1 = emb4[(size_t)(gp +  4) * 8 + l8];
        float4 v2 = emb4[(size_t)(gp +  8) * 8 + l8];
        float4 v3 = emb4[(size_t)(gp + 12) * 8 + l8];
        int k0 = __ldg(lab + gp);
        int k1 = __ldg(lab + gp + 4);
        int k2 = __ldg(lab + gp + 8);
        int k3 = __ldg(lab + gp + 12);

        // cache packed labels for phase 2 (one STS.32 from 4 lanes)
        if (l8 == 0)
            s_lab32[(p0 >> 4) * 4 + sub] =
                (unsigned)k0 | ((unsigned)k1 << 8) | ((unsigned)k2 << 16) | ((unsigned)k3 << 24);

#pragma unroll
        for (int h = 0; h < 4; h++) {
            float4 v = (h == 0) ? v0 : (h == 1) ? v1 : (h == 2) ? v2 : v3;
            int k    = (h == 0) ? k0 : (h == 1) ? k1 : (h == 2) ? k2 : k3;
            unsigned m = __match_any_sync(FULLM, k);
            bool all_distinct = __all_sync(FULLM, __popc(m) == 8);
            int idx = k * 8 + l8;
            if (all_distinct) {
                // warp-uniform converged path: issue-order smem RMW is safe
                float4 a = s_sum[w][idx];
                a.x += v.x; a.y += v.y; a.z += v.z; a.w += v.w;
                s_sum[w][idx] = a;
                if (l8 == 0) s_cnt1[w][k] += 1.f;
            } else {
#pragma unroll
                for (int s = 0; s < 4; s++) {
                    if (sub == s) {
                        float4 a = s_sum[w][idx];
                        a.x += v.x; a.y += v.y; a.z += v.z; a.w += v.w;
                        s_sum[w][idx] = a;
                        if (l8 == 0) s_cnt1[w][k] += 1.f;
                    }
                    __syncwarp();
                }
            }
        }
    }
    __syncthreads();

    // merge warp copies -> global (spread atomics over 8448 addrs)
    float* gs = (float*)g_sums4;
    const float* flat0 = (const float*)dyn;
    const size_t wstride = (size_t)Kk * 8 * 4;     // floats per warp copy
    for (int i = tid; i < Kk * Ee; i += TT) {
        float s = 0.f;
#pragma unroll
        for (int ww = 0; ww < WW; ww++) s += flat0[ww * wstride + i];
        atomicAdd(gs + b * Kk * Ee + i, s);
    }
    for (int i = tid; i < Kk; i += TT) {
        float s = 0.f;
#pragma unroll
        for (int ww = 0; ww < WW; ww++) s += s_cnt1[ww][i];
        atomicAdd(&g_counts[b * Kk + i], s);
    }

    // ============ PER-BATCH TICKET SYNC (32 blocks, all resident) ==========
    __threadfence();             // release our phase-1 contributions
    __syncthreads();
    if (tid == 0) {
        unsigned t = atomicAdd(&g_syncb[b], 1u);
        unsigned target = (t / BPB + 1u) * BPB;
        unsigned v;
        do {
            asm volatile("ld.acquire.gpu.u32 %0, [%1];" : "=r"(v) : "l"(&g_syncb[b]));
            if (v < target) __nanosleep(64);
        } while (v < target);
    }
    __syncthreads();

    // ================= PHASE 2: weighted hinge, register accumulation ======
    for (int i = tid; i < Kk * 8; i += TT) {
        float c_ = g_counts[b * Kk + (i >> 3)];
        float inv = 1.f / fmaxf(c_, 1.f);
        float4 s = g_sums4[b * Kk * 8 + i];
        s_c[i] = make_float4(s.x * inv, s.y * inv, s.z * inv, s.w * inv);
    }
    if (tid < Kk) {
        float c_ = g_counts[b * Kk + tid];
        s_cnt[tid] = c_;
        s_w[tid] = (tid > 0) ? 1.f / fmaxf(c_, 1.f) : 0.f;
    }
    __syncthreads();

    float acc = 0.f;            // per-thread sum of hinge/count[label]

    for (int p0 = w * 16; p0 < PPB; p0 += WW * 16) {
        int gp = base + p0 + sub;
        float4 v0 = emb4[(size_t)(gp     ) * 8 + l8];
        float4 v1 = emb4[(size_t)(gp +  4) * 8 + l8];
        float4 v2 = emb4[(size_t)(gp +  8) * 8 + l8];
        float4 v3 = emb4[(size_t)(gp + 12) * 8 + l8];
        // labels from smem cache: one broadcast LDS.32 + byte extracts
        unsigned packed = s_lab32[(p0 >> 4) * 4 + sub];
        int k0 = packed & 0xFF;
        int k1 = (packed >> 8) & 0xFF;
        int k2 = (packed >> 16) & 0xFF;
        int k3 = (packed >> 24);

        float4 c0 = s_c[k0 * 8 + l8];
        float4 c1 = s_c[k1 * 8 + l8];
        float4 c2 = s_c[k2 * 8 + l8];
        float4 c3 = s_c[k3 * 8 + l8];

        float dx, dy, dz, dw;
        dx = v0.x - c0.x; dy = v0.y - c0.y; dz = v0.z - c0.z; dw = v0.w - c0.w;
        float d2_0 = dx * dx + dy * dy + dz * dz + dw * dw;
        dx = v1.x - c1.x; dy = v1.y - c1.y; dz = v1.z - c1.z; dw = v1.w - c1.w;
        float d2_1 = dx * dx + dy * dy + dz * dz + dw * dw;
        dx = v2.x - c2.x; dy = v2.y - c2.y; dz = v2.z - c2.z; dw = v2.w - c2.w;
        float d2_2 = dx * dx + dy * dy + dz * dz + dw * dw;
        dx = v3.x - c3.x; dy = v3.y - c3.y; dz = v3.z - c3.z; dw = v3.w - c3.w;
        float d2_3 = dx * dx + dy * dy + dz * dz + dw * dw;

#pragma unroll
        for (int off = 1; off <= 4; off <<= 1) {
            d2_0 += __shfl_xor_sync(FULLM, d2_0, off);
            d2_1 += __shfl_xor_sync(FULLM, d2_1, off);
            d2_2 += __shfl_xor_sync(FULLM, d2_2, off);
            d2_3 += __shfl_xor_sync(FULLM, d2_3, off);
        }
        if (l8 == 0) {
            float h0 = sqrtf(fmaxf(d2_0, EPSX)) - DELTA_V;
            float h1 = sqrtf(fmaxf(d2_1, EPSX)) - DELTA_V;
            float h2 = sqrtf(fmaxf(d2_2, EPSX)) - DELTA_V;
            float h3 = sqrtf(fmaxf(d2_3, EPSX)) - DELTA_V;
            if (h0 > 0.f) acc += h0 * s_w[k0];
            if (h1 > 0.f) acc += h1 * s_w[k1];
            if (h2 > 0.f) acc += h2 * s_w[k2];
            if (h3 > 0.f) acc += h3 * s_w[k3];
        }
    }

    // block-reduce acc -> one global atomic per block
#pragma unroll
    for (int off = 16; off; off >>= 1) acc += __shfl_xor_sync(FULLM, acc, off);
    if (lane == 0) red[0][w] = acc;
    __syncthreads();
    if (tid == 0) {
        float s = 0.f;
#pragma unroll
        for (int ww = 0; ww < WW; ww++) s += red[0][ww];
        atomicAdd(&g_var[b], s);
    }

    // ================= per-batch finalize: last-block-done =================
    __threadfence();
    __syncthreads();
    if (tid == 0) {
        int done = atomicAdd(&g_ctr[b], 1);
        s_flag = (done == BPB - 1) ? 1 : 0;
    }
    __syncthreads();
    if (!s_flag) return;
    __threadfence();            // acquire: all blocks' g_var now visible

    float reg_acc = 0.f, pair_acc = 0.f;

    if (tid >= 1 && tid < Kk && s_cnt[tid] > 0.f) {
        int k = tid;
        float n2 = 0.f;
#pragma unroll
        for (int j = 0; j < 8; j++) {
            float4 c = s_c[k * 8 + j];
            n2 += c.x * c.x + c.y * c.y + c.z * c.z + c.w * c.w;
        }
        reg_acc = sqrtf(fmaxf(n2, EPSX));
    }

    for (int pi = tid; pi < Kk * Kk; pi += TT) {
        int i = pi / Kk, j = pi % Kk;
        if (i >= 1 && j > i && s_cnt[i] > 0.f && s_cnt[j] > 0.f) {
            float d2 = 0.f;
#pragma unroll
            for (int e = 0; e < 8; e++) {
                float4 a = s_c[i * 8 + e], bb = s_c[j * 8 + e];
                float ex = a.x - bb.x, ey = a.y - bb.y, ez = a.z - bb.z, ew = a.w - bb.w;
                d2 += ex * ex + ey * ey + ez * ez + ew * ew;
            }
            float cd = sqrtf(fmaxf(d2, EPSX));
            pair_acc += fmaxf(2.f * DELTA_D - cd, 0.f);
        }
    }

#pragma unroll
    for (int off = 16; off; off >>= 1) {
        reg_acc  += __shfl_xor_sync(FULLM, reg_acc, off);
        pair_acc += __shfl_xor_sync(FULLM, pair_acc, off);
    }
    if (lane == 0) { red[1][w] = reg_acc; red[2][w] = pair_acc; }
    __syncthreads();

    // ---- self-clean this batch's scratch for the next graph replay ----
    for (int i = tid; i < Kk * 8; i += TT)
        g_sums4[b * Kk * 8 + i] = make_float4(0.f, 0.f, 0.f, 0.f);
    for (int i = tid; i < Kk; i += TT) g_counts[b * Kk + i] = 0.f;

    if (tid == 0) {
        float reg_s = 0.f, pair_s = 0.f;
#pragma unroll
        for (int ww = 0; ww < WW; ww++) { reg_s += red[1][ww]; pair_s += red[2][ww]; }
        float ni = 0.f;
        for (int k = 1; k < Kk; k++) ni += (s_cnt[k] > 0.f) ? 1.f : 0.f;
        float var_t = g_var[b] / fmaxf(ni, 1.f);
        float npairs = ni * (ni - 1.f) * 0.5f;
        float dist_t = pair_s / fmaxf(npairs, 1.f);
        float reg_t = reg_s / fmaxf(ni, 1.f);
        float pb = var_t + dist_t + GAMMA * reg_t;
        if (!(ni > 0.f)) pb = 0.f;

        g_part[b] = pb;          // plain store (overwritten every run)
        g_var[b] = 0.f;
        g_ctr[b] = 0;
        __threadfence();         // release g_part before finalize ticket

        // last finalizer across batches sums partials and stores out[0]
        unsigned t = atomicAdd(&g_fin, 1u);
        if ((t % (unsigned)Bz) == (unsigned)(Bz - 1)) {
            __threadfence();     // acquire all g_part stores
            float s = 0.f;
#pragma unroll
            for (int bb = 0; bb < Bz; bb++) s += g_part[bb];
            out[0] = s / (float)Bz;
        }
    }
}

// ---------------------------------------------------------------------------
extern "C" void kernel_launch(void* const* d_in, const int* in_sizes, int n_in,
                              void* d_out, int out_size) {
    const float4* emb4 = (const float4*)d_in[0];
    const int* lab = (const int*)d_in[1];
    float* out = (float*)d_out;

    const int dynBytes = WW * Kk * 8 * sizeof(float4) + WW * Kk * sizeof(float); // 69696B
    static int attr_set = 0;
    if (!attr_set) {
        cudaFuncSetAttribute(fused_kernel, cudaFuncAttributeMaxDynamicSharedMemorySize, dynBytes);
        attr_set = 1;
    }
    fused_kernel<<<GRID, TT, dynBytes>>>(emb4, lab, out);
}

// round 16
// speedup vs baseline: 1.1124x; 1.1124x over previous
#include <cuda_runtime.h>

#define Bz 8
#define Nn 65536
#define Ee 32
#define Kk 33
#define BPB 32             // blocks per batch
#define PPB 2048           // points per block (no tail)
#define TT 512
#define WW (TT / 32)       // 16 warps
#define GRID (Bz * BPB)    // 256 blocks; all resident at 2 blocks/SM

#define DELTA_V 0.5f
#define DELTA_D 1.5f
#define GAMMA 0.001f
#define EPSX 1e-12f
#define FULLM 0xFFFFFFFFu

// Scratch (allocation-free rule: __device__ globals, zero-init at load;
// cleaned/overwritten each run so graph replays stay deterministic).
__device__ float4 g_sums4[Bz * Kk * 8];   // [b][k][e/4]
__device__ float  g_counts[Bz * Kk];
__device__ float  g_var[Bz];              // sum over points of hinge/count[label]
__device__ float  g_part[Bz];             // per-batch loss (overwritten each run)
__device__ int    g_ctr[Bz];              // finalize election (reset each run)
__device__ unsigned int g_syncb[Bz];      // per-batch monotone ticket counters
__device__ unsigned int g_fin;            // monotone finalize ticket

// 256-bit global load (sm_103a supports ld.global.v8.b32; 32B-aligned addr)
__device__ __forceinline__ void ldg256(const float4* p, float4& a, float4& b) {
    unsigned r0, r1, r2, r3, r4, r5, r6, r7;
    asm("ld.global.v8.b32 {%0,%1,%2,%3,%4,%5,%6,%7}, [%8];"
        : "=r"(r0), "=r"(r1), "=r"(r2), "=r"(r3),
          "=r"(r4), "=r"(r5), "=r"(r6), "=r"(r7) : "l"(p));
    a.x = __uint_as_float(r0); a.y = __uint_as_float(r1);
    a.z = __uint_as_float(r2); a.w = __uint_as_float(r3);
    b.x = __uint_as_float(r4); b.y = __uint_as_float(r5);
    b.z = __uint_as_float(r6); b.w = __uint_as_float(r7);
}

__device__ __forceinline__ float sq8(const float4& a0, const float4& a1,
                                     const float4& c0, const float4& c1) {
    float dx = a0.x - c0.x, dy = a0.y - c0.y, dz = a0.z - c0.z, dw = a0.w - c0.w;
    float s = dx * dx + dy * dy + dz * dz + dw * dw;
    dx = a1.x - c1.x; dy = a1.y - c1.y; dz = a1.z - c1.z; dw = a1.w - c1.w;
    return s + dx * dx + dy * dy + dz * dz + dw * dw;
}

// ---------------------------------------------------------------------------
// Fused persistent kernel: phase 1 (sums/counts, 8-lane layout) ->
// per-batch ticket sync -> phase 2 (weighted hinge, 4-lane layout, LDG.256)
// -> per-batch finalize -> last finalizer stores out[0].
// ---------------------------------------------------------------------------
__global__ void __launch_bounds__(TT, 2) fused_kernel(const float4* __restrict__ emb4,
                                                      const int* __restrict__ lab,
                                                      float* __restrict__ out) {
    // dynamic smem: phase-1 per-warp accumulators only
    extern __shared__ char dyn[];
    float4 (*s_sum)[Kk * 8] = (float4 (*)[Kk * 8])dyn;
    float  (*s_cnt1)[Kk]    = (float (*)[Kk])(dyn + (size_t)WW * Kk * 8 * sizeof(float4));

    // static: phase-2/finalize working set (padded centers: stride 9 float4s
    // = 144B rows so 4-lane LDS has ~2-way instead of 8-way bank conflicts)
    __shared__ float4 s_cp[Kk * 9];
    __shared__ float  s_cnt[Kk];
    __shared__ float  s_w[Kk];               // (k>0) ? 1/count : 0
    __shared__ float  red[3][WW];
    __shared__ int    s_flag;

    int tid = threadIdx.x;
    int w = tid >> 5;
    int lane = tid & 31;
    int sub = lane >> 3;     // phase 1: which of 4 points in a quarter
    int l8  = lane & 7;      // phase 1: float4 slot within the point

    int b = blockIdx.x / BPB;
    int base = b * Nn + (blockIdx.x % BPB) * PPB;

    // ================= PHASE 1: segment sums + counts (8-lane) ============
    for (int i = lane; i < Kk * 8; i += 32) s_sum[w][i] = make_float4(0.f, 0.f, 0.f, 0.f);
    for (int i = lane; i < Kk; i += 32) s_cnt1[w][i] = 0.f;
    __syncwarp();

    for (int p0 = w * 16; p0 < PPB; p0 += WW * 16) {     // 16 pts/warp-iter
        int gp = base + p0 + sub;
        float4 v0 = emb4[(size_t)(gp     ) * 8 + l8];
        float4 v1 = emb4[(size_t)(gp +  4) * 8 + l8];
        float4 v2 = emb4[(size_t)(gp +  8) * 8 + l8];
        float4 v3 = emb4[(size_t)(gp + 12) * 8 + l8];
        int k0 = __ldg(lab + gp);
        int k1 = __ldg(lab + gp + 4);
        int k2 = __ldg(lab + gp + 8);
        int k3 = __ldg(lab + gp + 12);

#pragma unroll
        for (int h = 0; h < 4; h++) {
            float4 v = (h == 0) ? v0 : (h == 1) ? v1 : (h == 2) ? v2 : v3;
            int k    = (h == 0) ? k0 : (h == 1) ? k1 : (h == 2) ? k2 : k3;
            unsigned m = __match_any_sync(FULLM, k);
            bool all_distinct = __all_sync(FULLM, __popc(m) == 8);
            int idx = k * 8 + l8;
            if (all_distinct) {
                // warp-uniform converged path: issue-order smem RMW is safe
                float4 a = s_sum[w][idx];
                a.x += v.x; a.y += v.y; a.z += v.z; a.w += v.w;
                s_sum[w][idx] = a;
                if (l8 == 0) s_cnt1[w][k] += 1.f;
            } else {
#pragma unroll
                for (int s = 0; s < 4; s++) {
                    if (sub == s) {
                        float4 a = s_sum[w][idx];
                        a.x += v.x; a.y += v.y; a.z += v.z; a.w += v.w;
                        s_sum[w][idx] = a;
                        if (l8 == 0) s_cnt1[w][k] += 1.f;
                    }
                    __syncwarp();
                }
            }
        }
    }
    __syncthreads();

    // merge warp copies -> global (spread atomics over 8448 addrs)
    float* gs = (float*)g_sums4;
    const float* flat0 = (const float*)dyn;
    const size_t wstride = (size_t)Kk * 8 * 4;     // floats per warp copy
    for (int i = tid; i < Kk * Ee; i += TT) {
        float s = 0.f;
#pragma unroll
        for (int ww = 0; ww < WW; ww++) s += flat0[ww * wstride + i];
        atomicAdd(gs + b * Kk * Ee + i, s);
    }
    for (int i = tid; i < Kk; i += TT) {
        float s = 0.f;
#pragma unroll
        for (int ww = 0; ww < WW; ww++) s += s_cnt1[ww][i];
        atomicAdd(&g_counts[b * Kk + i], s);
    }

    // ============ PER-BATCH TICKET SYNC (32 blocks, all resident) ==========
    __threadfence();             // release our phase-1 contributions
    __syncthreads();
    if (tid == 0) {
        unsigned t = atomicAdd(&g_syncb[b], 1u);
        unsigned target = (t / BPB + 1u) * BPB;
        unsigned v;
        do {
            asm volatile("ld.acquire.gpu.u32 %0, [%1];" : "=r"(v) : "l"(&g_syncb[b]));
            if (v < target) __nanosleep(64);
        } while (v < target);
    }
    __syncthreads();

    // ================= PHASE 2: weighted hinge (4-lane, LDG.256) ==========
    for (int i = tid; i < Kk * 8; i += TT) {
        int k = i >> 3, j = i & 7;
        float c_ = g_counts[b * Kk + k];
        float inv = 1.f / fmaxf(c_, 1.f);
        float4 s = g_sums4[b * Kk * 8 + i];
        s_cp[k * 9 + j] = make_float4(s.x * inv, s.y * inv, s.z * inv, s.w * inv);
    }
    if (tid < Kk) {
        float c_ = g_counts[b * Kk + tid];
        s_cnt[tid] = c_;
        s_w[tid] = (tid > 0) ? 1.f / fmaxf(c_, 1.f) : 0.f;
    }
    __syncthreads();

    int g4 = lane >> 2;          // point within 8-point row
    int l4 = lane & 3;           // 8-elem slice within the point
    float acc = 0.f;             // per-thread sum of hinge/count[label]

    for (int p0 = w * 16; p0 < PPB; p0 += WW * 16) {
        int gpA = base + p0 + g4;          // row A: 8 points
        int gpB = gpA + 8;                 // row B: 8 points
        float4 a0, a1, b0, b1;
        ldg256(emb4 + (size_t)gpA * 8 + l4 * 2, a0, a1);   // 1KB dense per row
        ldg256(emb4 + (size_t)gpB * 8 + l4 * 2, b0, b1);
        int kA = __ldg(lab + gpA);
        int kB = __ldg(lab + gpB);

        float4 cA0 = s_cp[kA * 9 + l4 * 2], cA1 = s_cp[kA * 9 + l4 * 2 + 1];
        float4 cB0 = s_cp[kB * 9 + l4 * 2], cB1 = s_cp[kB * 9 + l4 * 2 + 1];

        float dA = sq8(a0, a1, cA0, cA1);
        float dB = sq8(b0, b1, cB0, cB1);

        dA += __shfl_xor_sync(FULLM, dA, 1);
        dA += __shfl_xor_sync(FULLM, dA, 2);
        dB += __shfl_xor_sync(FULLM, dB, 1);
        dB += __shfl_xor_sync(FULLM, dB, 2);

        if (l4 == 0) {
            float hA = sqrtf(fmaxf(dA, EPSX)) - DELTA_V;
            float hB = sqrtf(fmaxf(dB, EPSX)) - DELTA_V;
            if (hA > 0.f) acc += hA * s_w[kA];
            if (hB > 0.f) acc += hB * s_w[kB];
        }
    }

    // block-reduce acc -> one global atomic per block
#pragma unroll
    for (int off = 16; off; off >>= 1) acc += __shfl_xor_sync(FULLM, acc, off);
    if (lane == 0) red[0][w] = acc;
    __syncthreads();
    if (tid == 0) {
        float s = 0.f;
#pragma unroll
        for (int ww = 0; ww < WW; ww++) s += red[0][ww];
        atomicAdd(&g_var[b], s);
    }

    // ================= per-batch finalize: last-block-done =================
    __threadfence();
    __syncthreads();
    if (tid == 0) {
        int done = atomicAdd(&g_ctr[b], 1);
        s_flag = (done == BPB - 1) ? 1 : 0;
    }
    __syncthreads();
    if (!s_flag) return;
    __threadfence();            // acquire: all blocks' g_var now visible

    float reg_acc = 0.f, pair_acc = 0.f;

    if (tid >= 1 && tid < Kk && s_cnt[tid] > 0.f) {
        int k = tid;
        float n2 = 0.f;
#pragma unroll
        for (int j = 0; j < 8; j++) {
            float4 c = s_cp[k * 9 + j];
            n2 += c.x * c.x + c.y * c.y + c.z * c.z + c.w * c.w;
        }
        reg_acc = sqrtf(fmaxf(n2, EPSX));
    }

    for (int pi = tid; pi < Kk * Kk; pi += TT) {
        int i = pi / Kk, j = pi % Kk;
        if (i >= 1 && j > i && s_cnt[i] > 0.f && s_cnt[j] > 0.f) {
            float d2 = 0.f;
#pragma unroll
            for (int e = 0; e < 8; e++) {
                float4 a = s_cp[i * 9 + e], bb = s_cp[j * 9 + e];
                float ex = a.x - bb.x, ey = a.y - bb.y, ez = a.z - bb.z, ew = a.w - bb.w;
                d2 += ex * ex + ey * ey + ez * ez + ew * ew;
            }
            float cd = sqrtf(fmaxf(d2, EPSX));
            pair_acc += fmaxf(2.f * DELTA_D - cd, 0.f);
        }
    }

#pragma unroll
    for (int off = 16; off; off >>= 1) {
        reg_acc  += __shfl_xor_sync(FULLM, reg_acc, off);
        pair_acc += __shfl_xor_sync(FULLM, pair_acc, off);
    }
    if (lane == 0) { red[1][w] = reg_acc; red[2][w] = pair_acc; }
    __syncthreads();

    // ---- self-clean this batch's scratch for the next graph replay ----
    for (int i = tid; i < Kk * 8; i += TT)
        g_sums4[b * Kk * 8 + i] = make_float4(0.f, 0.f, 0.f, 0.f);
    for (int i = tid; i < Kk; i += TT) g_counts[b * Kk + i] = 0.f;

    if (tid == 0) {
        float reg_s = 0.f, pair_s = 0.f;
#pragma unroll
        for (int ww = 0; ww < WW; ww++) { reg_s += red[1][ww]; pair_s += red[2][ww]; }
        float ni = 0.f;
        for (int k = 1; k < Kk; k++) ni += (s_cnt[k] > 0.f) ? 1.f : 0.f;
        float var_t = g_var[b] / fmaxf(ni, 1.f);
        float npairs = ni * (ni - 1.f) * 0.5f;
        float dist_t = pair_s / fmaxf(npairs, 1.f);
        float reg_t = reg_s / fmaxf(ni, 1.f);
        float pb = var_t + dist_t + GAMMA * reg_t;
        if (!(ni > 0.f)) pb = 0.f;

        g_part[b] = pb;          // plain store (overwritten every run)
        g_var[b] = 0.f;
        g_ctr[b] = 0;
        __threadfence();         // release g_part before finalize ticket

        // last finalizer across batches sums partials and stores out[0]
        unsigned t = atomicAdd(&g_fin, 1u);
        if ((t % (unsigned)Bz) == (unsigned)(Bz - 1)) {
            __threadfence();     // acquire all g_part stores
            float s = 0.f;
#pragma unroll
            for (int bb = 0; bb < Bz; bb++) s += g_part[bb];
            out[0] = s / (float)Bz;
        }
    }
}

// ---------------------------------------------------------------------------
extern "C" void kernel_launch(void* const* d_in, const int* in_sizes, int n_in,
                              void* d_out, int out_size) {
    const float4* emb4 = (const float4*)d_in[0];
    const int* lab = (const int*)d_in[1];
    float* out = (float*)d_out;

    const int dynBytes = WW * Kk * 8 * sizeof(float4) + WW * Kk * sizeof(float); // 69696B
    static int attr_set = 0;
    if (!attr_set) {
        cudaFuncSetAttribute(fused_kernel, cudaFuncAttributeMaxDynamicSharedMemorySize, dynBytes);
        attr_set = 1;
    }
    fused_kernel<<<GRID, TT, dynBytes>>>(emb4, lab, out);
}